// round 4
// baseline (speedup 1.0000x reference)
#include <cuda_runtime.h>
#include <cstdint>

#define N_USERS 50000
#define N_ITEMS 20000
#define N_EDGES_C 1000000
#define NR 5
#define F 64
#define HID 64
#define KDIM 320          // NR * F

#define NBU (N_USERS * NR)        // 250000 user-side buckets
#define NBV (N_ITEMS * NR)        // 100000 item-side buckets
#define NB  (NBU + NBV)           // 350000

#define SCAN_TPB 256
#define SCAN_EPT 8
#define SCAN_BE  (SCAN_TPB * SCAN_EPT)           // 2048
#define SCAN_NBLK ((NB + SCAN_BE - 1) / SCAN_BE) // 171

// -------- scratch (device globals; no allocation allowed) --------
__device__ float g_acc_u[(size_t)N_USERS * NR * F];   // 64 MB  (scaled means)
__device__ float g_acc_v[(size_t)N_ITEMS * NR * F];   // 25.6 MB
__device__ int g_cnt[NB];
__device__ int g_scan[NB];
__device__ int g_off[NB + 1];
__device__ int g_cursor[NB];
__device__ int g_bsum[SCAN_NBLK];
__device__ int g_srcids[2 * N_EDGES_C];               // 8 MB

// ================= phase 0: zero bucket counts =================
__global__ void zero_cnt() {
    int i = blockIdx.x * blockDim.x + threadIdx.x;
    int stride = gridDim.x * blockDim.x;
    for (; i < NB; i += stride) g_cnt[i] = 0;
}

// ================= phase 1: histogram =================
__global__ void hist_kernel(const int* __restrict__ u_s,
                            const int* __restrict__ v_s,
                            const int* __restrict__ rate) {
    int e = blockIdx.x * blockDim.x + threadIdx.x;
    if (e >= N_EDGES_C) return;
    int u = u_s[e], v = v_s[e], r = rate[e];
    atomicAdd(&g_cnt[u * NR + r], 1);
    atomicAdd(&g_cnt[NBU + v * NR + r], 1);
}

// ================= phase 2: exclusive scan (3 kernels) =================
__global__ void scan_a() {
    __shared__ int s[SCAN_TPB];
    int t = threadIdx.x;
    int base = blockIdx.x * SCAN_BE + t * SCAN_EPT;
    int v[SCAN_EPT];
    int sum = 0;
    #pragma unroll
    for (int i = 0; i < SCAN_EPT; i++) {
        int idx = base + i;
        int c = (idx < NB) ? g_cnt[idx] : 0;
        v[i] = sum;           // exclusive within thread
        sum += c;
    }
    s[t] = sum;
    __syncthreads();
    for (int d = 1; d < SCAN_TPB; d <<= 1) {
        int x = (t >= d) ? s[t - d] : 0;
        __syncthreads();
        s[t] += x;
        __syncthreads();
    }
    int toff = (t > 0) ? s[t - 1] : 0;
    #pragma unroll
    for (int i = 0; i < SCAN_EPT; i++) {
        int idx = base + i;
        if (idx < NB) g_scan[idx] = toff + v[i];
    }
    if (t == SCAN_TPB - 1) g_bsum[blockIdx.x] = s[t];
}

__global__ void scan_b() {
    __shared__ int s[SCAN_TPB];
    int t = threadIdx.x;
    int x = (t < SCAN_NBLK) ? g_bsum[t] : 0;
    s[t] = x;
    __syncthreads();
    for (int d = 1; d < SCAN_TPB; d <<= 1) {
        int y = (t >= d) ? s[t - d] : 0;
        __syncthreads();
        s[t] += y;
        __syncthreads();
    }
    if (t < SCAN_NBLK) g_bsum[t] = (t > 0) ? s[t - 1] : 0;  // exclusive
}

__global__ void scan_c() {
    int idx = blockIdx.x * blockDim.x + threadIdx.x;
    if (idx >= NB) return;
    int off = g_scan[idx] + g_bsum[idx / SCAN_BE];
    g_off[idx] = off;
    g_cursor[idx] = off;
    if (idx == 0) g_off[NB] = 2 * N_EDGES_C;
}

// ================= phase 3: scatter edge src ids =================
__global__ void scatter_kernel(const int* __restrict__ u_s,
                               const int* __restrict__ v_s,
                               const int* __restrict__ rate) {
    int e = blockIdx.x * blockDim.x + threadIdx.x;
    if (e >= N_EDGES_C) return;
    int u = u_s[e], v = v_s[e], r = rate[e];
    int pu = atomicAdd(&g_cursor[u * NR + r], 1);
    g_srcids[pu] = v;                      // source is the item
    int pv = atomicAdd(&g_cursor[NBU + v * NR + r], 1);
    g_srcids[pv] = u;                      // source is the user
}

// ================= phase 4: gather + mean (one warp per bucket) =================
__global__ __launch_bounds__(256) void aggregate_kernel(const float* __restrict__ x_user,
                                                        const float* __restrict__ x_item) {
    int wid = (blockIdx.x * blockDim.x + threadIdx.x) >> 5;
    int lane = threadIdx.x & 31;
    if (wid >= NB) return;
    int begin = g_off[wid];
    int end = g_off[wid + 1];
    int n = end - begin;
    const float* __restrict__ feat = (wid < NBU) ? x_item : x_user;

    float ax = 0.f, ay = 0.f;
    int j = begin;
    while (j < end) {
        int m = min(32, end - j);
        int id = (lane < m) ? g_srcids[j + lane] : 0;
        int q = 0;
        for (; q + 4 <= m; q += 4) {
            int s0 = __shfl_sync(0xffffffffu, id, q + 0);
            int s1 = __shfl_sync(0xffffffffu, id, q + 1);
            int s2 = __shfl_sync(0xffffffffu, id, q + 2);
            int s3 = __shfl_sync(0xffffffffu, id, q + 3);
            float2 t0 = ((const float2*)(feat + (size_t)s0 * F))[lane];
            float2 t1 = ((const float2*)(feat + (size_t)s1 * F))[lane];
            float2 t2 = ((const float2*)(feat + (size_t)s2 * F))[lane];
            float2 t3 = ((const float2*)(feat + (size_t)s3 * F))[lane];
            ax += t0.x; ay += t0.y;
            ax += t1.x; ay += t1.y;
            ax += t2.x; ay += t2.y;
            ax += t3.x; ay += t3.y;
        }
        for (; q < m; q++) {
            int s0 = __shfl_sync(0xffffffffu, id, q);
            float2 t0 = ((const float2*)(feat + (size_t)s0 * F))[lane];
            ax += t0.x; ay += t0.y;
        }
        j += m;
    }
    float invc = (n > 0) ? 1.0f / (float)n : 0.0f;
    ax *= invc; ay *= invc;
    float2* dst = (wid < NBU)
        ? (float2*)(g_acc_u + (size_t)wid * F)
        : (float2*)(g_acc_v + (size_t)(wid - NBU) * F);
    dst[lane] = make_float2(ax, ay);
}

// ================= phase 5: out = acc @ Wflat  (M x 320 @ 320 x 64) =================
#define GBM 128
#define GKK 32
#define GPAD 8

__device__ __forceinline__ unsigned long long pack2(float a) {
    unsigned long long r;
    asm("mov.b64 %0, {%1, %1};" : "=l"(r) : "r"(__float_as_uint(a)));
    return r;
}
__device__ __forceinline__ void fma2(unsigned long long& d,
                                     unsigned long long a, unsigned long long b) {
    asm("fma.rn.f32x2 %0, %1, %2, %0;" : "+l"(d) : "l"(a), "l"(b));
}

__global__ __launch_bounds__(256) void out_gemm(int which,
                                                const float* __restrict__ W,
                                                float* __restrict__ out) {
    const float* __restrict__ A = which ? g_acc_v : g_acc_u;
    const int M = which ? N_ITEMS : N_USERS;

    __shared__ __align__(16) float Ast[GKK][GBM + GPAD];  // transposed A tile
    __shared__ __align__(16) float Bs[GKK][HID];

    int tid = threadIdx.x;
    int tx = tid & 15;     // cols tx*4 .. +3
    int ty = tid >> 4;     // rows ty*8 .. +7
    int rowBase = blockIdx.x * GBM;

    unsigned long long acc[4][4];  // [rowpair][col], each = {even row, odd row}
    #pragma unroll
    for (int p = 0; p < 4; p++)
        #pragma unroll
        for (int c = 0; c < 4; c++) acc[p][c] = 0ull;

    int lrow = tid >> 1;           // 0..127
    int lkb = (tid & 1) * 16;      // 0 or 16

    for (int k0 = 0; k0 < KDIM; k0 += GKK) {
        // ---- load A chunk [128 rows x 32 k], store transposed ----
        {
            int grow = rowBase + lrow;
            const float4* ap = (const float4*)(A + (size_t)grow * KDIM + k0 + lkb);
            #pragma unroll
            for (int h = 0; h < 4; h++) {
                float4 v = (grow < M) ? ap[h] : make_float4(0.f, 0.f, 0.f, 0.f);
                int kk = lkb + h * 4;
                Ast[kk + 0][lrow] = v.x;
                Ast[kk + 1][lrow] = v.y;
                Ast[kk + 2][lrow] = v.z;
                Ast[kk + 3][lrow] = v.w;
            }
        }
        // ---- load W chunk [32 x 64] = 512 float4, 2 per thread ----
        {
            const float4* wp = (const float4*)(W + (size_t)k0 * HID);
            float4* bsp = (float4*)(&Bs[0][0]);
            bsp[tid] = wp[tid];
            bsp[tid + 256] = wp[tid + 256];
        }
        __syncthreads();

        #pragma unroll
        for (int k = 0; k < GKK; k++) {
            // rows come out of shared already packed in f32 pairs
            ulonglong2 aA = *(const ulonglong2*)&Ast[k][ty * 8];       // rows 0-3
            ulonglong2 aB = *(const ulonglong2*)&Ast[k][ty * 8 + 4];   // rows 4-7
            float4 bv = *(const float4*)&Bs[k][tx * 4];
            unsigned long long b0 = pack2(bv.x);
            unsigned long long b1 = pack2(bv.y);
            unsigned long long b2 = pack2(bv.z);
            unsigned long long b3 = pack2(bv.w);
            fma2(acc[0][0], aA.x, b0); fma2(acc[0][1], aA.x, b1);
            fma2(acc[0][2], aA.x, b2); fma2(acc[0][3], aA.x, b3);
            fma2(acc[1][0], aA.y, b0); fma2(acc[1][1], aA.y, b1);
            fma2(acc[1][2], aA.y, b2); fma2(acc[1][3], aA.y, b3);
            fma2(acc[2][0], aB.x, b0); fma2(acc[2][1], aB.x, b1);
            fma2(acc[2][2], aB.x, b2); fma2(acc[2][3], aB.x, b3);
            fma2(acc[3][0], aB.y, b0); fma2(acc[3][1], aB.y, b1);
            fma2(acc[3][2], aB.y, b2); fma2(acc[3][3], aB.y, b3);
        }
        __syncthreads();
    }

    // ---- store: rowpair p covers rows ty*8 + 2p and +1 ----
    #pragma unroll
    for (int p = 0; p < 4; p++) {
        float2 c0 = *(float2*)&acc[p][0];
        float2 c1 = *(float2*)&acc[p][1];
        float2 c2 = *(float2*)&acc[p][2];
        float2 c3 = *(float2*)&acc[p][3];
        int re = rowBase + ty * 8 + 2 * p;
        if (re < M) {
            float4 o = make_float4(c0.x, c1.x, c2.x, c3.x);
            *(float4*)(out + (size_t)re * HID + tx * 4) = o;
        }
        if (re + 1 < M) {
            float4 o = make_float4(c0.y, c1.y, c2.y, c3.y);
            *(float4*)(out + (size_t)(re + 1) * HID + tx * 4) = o;
        }
    }
}

// ================= launch =================
extern "C" void kernel_launch(void* const* d_in, const int* in_sizes, int n_in,
                              void* d_out, int out_size) {
    const int*   u_s    = (const int*)d_in[0];
    const int*   v_s    = (const int*)d_in[1];
    const int*   rate   = (const int*)d_in[2];
    const float* x_user = (const float*)d_in[3];
    const float* x_item = (const float*)d_in[4];
    const float* weight = (const float*)d_in[5];
    float* out = (float*)d_out;
    (void)in_sizes; (void)n_in; (void)out_size;

    int ethreads = 256;
    int eblocks = (N_EDGES_C + ethreads - 1) / ethreads;

    zero_cnt<<<512, 256>>>();
    hist_kernel<<<eblocks, ethreads>>>(u_s, v_s, rate);
    scan_a<<<SCAN_NBLK, SCAN_TPB>>>();
    scan_b<<<1, SCAN_TPB>>>();
    scan_c<<<(NB + 255) / 256, 256>>>();
    scatter_kernel<<<eblocks, ethreads>>>(u_s, v_s, rate);

    int awarps = NB;                       // one warp per bucket
    int ablocks = (awarps + 7) / 8;        // 8 warps per block
    aggregate_kernel<<<ablocks, 256>>>(x_user, x_item);

    out_gemm<<<(N_USERS + GBM - 1) / GBM, 256>>>(0, weight, out);
    out_gemm<<<(N_ITEMS + GBM - 1) / GBM, 256>>>(1, weight, out + (size_t)N_USERS * HID);
}

// round 9
// speedup vs baseline: 1.1183x; 1.1183x over previous
#include <cuda_runtime.h>
#include <cstdint>

#define N_USERS 50000
#define N_ITEMS 20000
#define N_EDGES_C 1000000
#define NR 5
#define F 64
#define HID 64
#define KDIM 320          // NR * F

#define NBU (N_USERS * NR)        // 250000
#define NBV (N_ITEMS * NR)        // 100000
#define NB  (NBU + NBV)           // 350000

#define SCAN_TPB 256
#define SCAN_EPT 8
#define SCAN_BE  (SCAN_TPB * SCAN_EPT)           // 2048
#define SCAN_NBLK ((NB + SCAN_BE - 1) / SCAN_BE) // 171

// -------- scratch (device globals) --------
__device__ float g_acc_u[(size_t)N_USERS * KDIM];   // 64 MB (scaled means)
__device__ float g_acc_v[(size_t)N_ITEMS * KDIM];   // 25.6 MB
__device__ int g_cnt[NB];
__device__ int g_scan[NB];
__device__ int g_off[NB + 1];
__device__ int g_cursor[NB];
__device__ int g_bsum[SCAN_NBLK];
__device__ int g_srcids[2 * N_EDGES_C];             // 8 MB

// ============ phase 0: zero bucket counts ============
__global__ void zero_cnt() {
    int i = blockIdx.x * blockDim.x + threadIdx.x;
    int st = gridDim.x * blockDim.x;
    for (int j = i; j < NB; j += st) g_cnt[j] = 0;
}

// ============ phase 1: histogram ============
__global__ void hist_kernel(const int* __restrict__ u_s,
                            const int* __restrict__ v_s,
                            const int* __restrict__ rate) {
    int e = blockIdx.x * blockDim.x + threadIdx.x;
    if (e >= N_EDGES_C) return;
    int u = u_s[e], v = v_s[e], r = rate[e];
    atomicAdd(&g_cnt[u * NR + r], 1);
    atomicAdd(&g_cnt[NBU + v * NR + r], 1);
}

// ============ phase 2a: per-chunk scan ============
__global__ void scan_a() {
    __shared__ int s[SCAN_TPB];
    int t = threadIdx.x;
    int base = blockIdx.x * SCAN_BE + t * SCAN_EPT;
    int v[SCAN_EPT];
    int sum = 0;
    #pragma unroll
    for (int i = 0; i < SCAN_EPT; i++) {
        int idx = base + i;
        int c = (idx < NB) ? g_cnt[idx] : 0;
        v[i] = sum;
        sum += c;
    }
    s[t] = sum;
    __syncthreads();
    for (int d = 1; d < SCAN_TPB; d <<= 1) {
        int x = (t >= d) ? s[t - d] : 0;
        __syncthreads();
        s[t] += x;
        __syncthreads();
    }
    int toff = (t > 0) ? s[t - 1] : 0;
    #pragma unroll
    for (int i = 0; i < SCAN_EPT; i++) {
        int idx = base + i;
        if (idx < NB) g_scan[idx] = toff + v[i];
    }
    if (t == SCAN_TPB - 1) g_bsum[blockIdx.x] = s[t];
}

// ============ phase 2b: apply chunk prefixes (merged) ============
// Each 256-thread block covers 256 consecutive indices; all lie in one 2048-chunk.
__global__ void scan_bc() {
    __shared__ int s[256];
    int t = threadIdx.x;
    int chunk = blockIdx.x >> 3;
    int x = (t < chunk && t < SCAN_NBLK) ? g_bsum[t] : 0;
    s[t] = x;
    __syncthreads();
    for (int d = 128; d > 0; d >>= 1) {
        if (t < d) s[t] += s[t + d];
        __syncthreads();
    }
    int prefix = s[0];
    int idx = blockIdx.x * 256 + t;
    if (idx < NB) {
        int off = g_scan[idx] + prefix;
        g_off[idx] = off;
        g_cursor[idx] = off;
    }
    if (idx == 0) g_off[NB] = 2 * N_EDGES_C;
}

// ============ phase 3: scatter edge src ids ============
__global__ void scatter_kernel(const int* __restrict__ u_s,
                               const int* __restrict__ v_s,
                               const int* __restrict__ rate) {
    int e = blockIdx.x * blockDim.x + threadIdx.x;
    if (e >= N_EDGES_C) return;
    int u = u_s[e], v = v_s[e], r = rate[e];
    int pu = atomicAdd(&g_cursor[u * NR + r], 1);
    g_srcids[pu] = v;
    int pv = atomicAdd(&g_cursor[NBU + v * NR + r], 1);
    g_srcids[pv] = u;
}

// ============ phase 4: gather + mean, one warp per NODE (5 buckets, fp32) ============
__global__ __launch_bounds__(256) void aggregate_kernel(const float* __restrict__ x_user,
                                                        const float* __restrict__ x_item) {
    int wid = (blockIdx.x * blockDim.x + threadIdx.x) >> 5;
    int lane = threadIdx.x & 31;
    if (wid >= N_USERS + N_ITEMS) return;

    int bb;
    const float* __restrict__ feat;
    float* dst;
    if (wid < N_USERS) {
        bb = wid * NR;
        feat = x_item;
        dst = g_acc_u + (size_t)wid * KDIM;
    } else {
        int v = wid - N_USERS;
        bb = NBU + v * NR;
        feat = x_user;
        dst = g_acc_v + (size_t)v * KDIM;
    }

    // lanes 0..5 fetch the 6 offsets bounding this node's 5 buckets
    int o = (lane <= NR) ? g_off[bb + lane] : 0;

    float2 m[NR];
    #pragma unroll
    for (int r = 0; r < NR; r++) m[r] = make_float2(0.f, 0.f);

    #pragma unroll
    for (int r = 0; r < NR; r++) {
        int begin = __shfl_sync(0xffffffffu, o, r);
        int end   = __shfl_sync(0xffffffffu, o, r + 1);
        int j = begin;
        while (j < end) {
            int mm = min(32, end - j);
            int id = (lane < mm) ? g_srcids[j + lane] : 0;
            int q = 0;
            for (; q + 4 <= mm; q += 4) {
                int s0 = __shfl_sync(0xffffffffu, id, q + 0);
                int s1 = __shfl_sync(0xffffffffu, id, q + 1);
                int s2 = __shfl_sync(0xffffffffu, id, q + 2);
                int s3 = __shfl_sync(0xffffffffu, id, q + 3);
                float2 t0 = ((const float2*)(feat + (size_t)s0 * F))[lane];
                float2 t1 = ((const float2*)(feat + (size_t)s1 * F))[lane];
                float2 t2 = ((const float2*)(feat + (size_t)s2 * F))[lane];
                float2 t3 = ((const float2*)(feat + (size_t)s3 * F))[lane];
                m[r].x += t0.x + t1.x + t2.x + t3.x;
                m[r].y += t0.y + t1.y + t2.y + t3.y;
            }
            for (; q < mm; q++) {
                int s0 = __shfl_sync(0xffffffffu, id, q);
                float2 t0 = ((const float2*)(feat + (size_t)s0 * F))[lane];
                m[r].x += t0.x;
                m[r].y += t0.y;
            }
            j += mm;
        }
        int n = end - begin;
        float invc = (n > 0) ? 1.0f / (float)n : 0.0f;
        m[r].x *= invc;
        m[r].y *= invc;
    }

    // store 5 adjacent 256B rows (1280B contiguous per warp)
    #pragma unroll
    for (int r = 0; r < NR; r++)
        ((float2*)(dst + r * F))[lane] = m[r];
}

// ============ phase 5: out = acc @ Wflat  (M x 320 @ 320 x 64, fp32) ============
#define GBM 128
#define GKK 32
#define GPAD 8

__device__ __forceinline__ unsigned long long pack2(float a) {
    unsigned long long r;
    asm("mov.b64 %0, {%1, %1};" : "=l"(r) : "r"(__float_as_uint(a)));
    return r;
}
__device__ __forceinline__ void fma2(unsigned long long& d,
                                     unsigned long long a, unsigned long long b) {
    asm("fma.rn.f32x2 %0, %1, %2, %0;" : "+l"(d) : "l"(a), "l"(b));
}

__global__ __launch_bounds__(256) void out_gemm(int which,
                                                const float* __restrict__ W,
                                                float* __restrict__ out) {
    const float* __restrict__ A = which ? g_acc_v : g_acc_u;
    const int M = which ? N_ITEMS : N_USERS;

    __shared__ __align__(16) float Ast[GKK][GBM + GPAD];  // transposed A tile
    __shared__ __align__(16) float Bs[GKK][HID];

    int tid = threadIdx.x;
    int tx = tid & 15;     // cols tx*4 .. +3
    int ty = tid >> 4;     // rows ty*8 .. +7
    int rowBase = blockIdx.x * GBM;

    unsigned long long acc[4][4];  // [rowpair][col] = {even row, odd row}
    #pragma unroll
    for (int p = 0; p < 4; p++)
        #pragma unroll
        for (int c = 0; c < 4; c++) acc[p][c] = 0ull;

    int lrow = tid >> 1;           // 0..127
    int lkb = (tid & 1) * 16;      // 0 or 16

    for (int k0 = 0; k0 < KDIM; k0 += GKK) {
        // ---- load A chunk [128 rows x 32 k], store transposed ----
        {
            int grow = rowBase + lrow;
            const float4* ap = (const float4*)(A + (size_t)grow * KDIM + k0 + lkb);
            #pragma unroll
            for (int h = 0; h < 4; h++) {
                float4 v = (grow < M) ? ap[h] : make_float4(0.f, 0.f, 0.f, 0.f);
                int kk = lkb + h * 4;
                Ast[kk + 0][lrow] = v.x;
                Ast[kk + 1][lrow] = v.y;
                Ast[kk + 2][lrow] = v.z;
                Ast[kk + 3][lrow] = v.w;
            }
        }
        // ---- load W chunk [32 x 64] = 512 float4, 2 per thread ----
        {
            const float4* wp = (const float4*)(W + (size_t)k0 * HID);
            float4* bsp = (float4*)(&Bs[0][0]);
            bsp[tid] = wp[tid];
            bsp[tid + 256] = wp[tid + 256];
        }
        __syncthreads();

        #pragma unroll
        for (int k = 0; k < GKK; k++) {
            ulonglong2 aA = *(const ulonglong2*)&Ast[k][ty * 8];       // rows 0-3
            ulonglong2 aB = *(const ulonglong2*)&Ast[k][ty * 8 + 4];   // rows 4-7
            float4 bv = *(const float4*)&Bs[k][tx * 4];
            unsigned long long b0 = pack2(bv.x);
            unsigned long long b1 = pack2(bv.y);
            unsigned long long b2 = pack2(bv.z);
            unsigned long long b3 = pack2(bv.w);
            fma2(acc[0][0], aA.x, b0); fma2(acc[0][1], aA.x, b1);
            fma2(acc[0][2], aA.x, b2); fma2(acc[0][3], aA.x, b3);
            fma2(acc[1][0], aA.y, b0); fma2(acc[1][1], aA.y, b1);
            fma2(acc[1][2], aA.y, b2); fma2(acc[1][3], aA.y, b3);
            fma2(acc[2][0], aB.x, b0); fma2(acc[2][1], aB.x, b1);
            fma2(acc[2][2], aB.x, b2); fma2(acc[2][3], aB.x, b3);
            fma2(acc[3][0], aB.y, b0); fma2(acc[3][1], aB.y, b1);
            fma2(acc[3][2], aB.y, b2); fma2(acc[3][3], aB.y, b3);
        }
        __syncthreads();
    }

    // rowpair p covers rows ty*8 + 2p and +1
    #pragma unroll
    for (int p = 0; p < 4; p++) {
        float2 c0 = *(float2*)&acc[p][0];
        float2 c1 = *(float2*)&acc[p][1];
        float2 c2 = *(float2*)&acc[p][2];
        float2 c3 = *(float2*)&acc[p][3];
        int re = rowBase + ty * 8 + 2 * p;
        if (re < M) {
            float4 oo = make_float4(c0.x, c1.x, c2.x, c3.x);
            *(float4*)(out + (size_t)re * HID + tx * 4) = oo;
        }
        if (re + 1 < M) {
            float4 oo = make_float4(c0.y, c1.y, c2.y, c3.y);
            *(float4*)(out + (size_t)(re + 1) * HID + tx * 4) = oo;
        }
    }
}

// ============ launch ============
extern "C" void kernel_launch(void* const* d_in, const int* in_sizes, int n_in,
                              void* d_out, int out_size) {
    const int*   u_s    = (const int*)d_in[0];
    const int*   v_s    = (const int*)d_in[1];
    const int*   rate   = (const int*)d_in[2];
    const float* x_user = (const float*)d_in[3];
    const float* x_item = (const float*)d_in[4];
    const float* weight = (const float*)d_in[5];
    float* out = (float*)d_out;
    (void)in_sizes; (void)n_in; (void)out_size;

    int ethreads = 256;
    int eblocks = (N_EDGES_C + ethreads - 1) / ethreads;

    zero_cnt<<<512, 256>>>();
    hist_kernel<<<eblocks, ethreads>>>(u_s, v_s, rate);
    scan_a<<<SCAN_NBLK, SCAN_TPB>>>();
    scan_bc<<<(NB + 255) / 256, 256>>>();
    scatter_kernel<<<eblocks, ethreads>>>(u_s, v_s, rate);

    int nwarps = N_USERS + N_ITEMS;        // one warp per node
    int ablocks = (nwarps + 7) / 8;
    aggregate_kernel<<<ablocks, 256>>>(x_user, x_item);

    out_gemm<<<(N_USERS + GBM - 1) / GBM, 256>>>(0, weight, out);
    out_gemm<<<(N_ITEMS + GBM - 1) / GBM, 256>>>(1, weight, out + (size_t)N_USERS * HID);
}

// round 16
// speedup vs baseline: 1.2441x; 1.1125x over previous
#include <cuda_runtime.h>
#include <cuda_fp16.h>
#include <cstdint>

#define N_USERS 50000
#define N_ITEMS 20000
#define N_EDGES_C 1000000
#define NR 5
#define F 64
#define HID 64
#define KDIM 320          // NR * F

#define NBU (N_USERS * NR)        // 250000
#define NBV (N_ITEMS * NR)        // 100000
#define NB  (NBU + NBV)           // 350000

#define SCAN_TPB 256
#define SCAN_EPT 8
#define SCAN_BE  (SCAN_TPB * SCAN_EPT)           // 2048
#define SCAN_NBLK ((NB + SCAN_BE - 1) / SCAN_BE) // 171

// -------- scratch (device globals) --------
__device__ __half g_y_user[(size_t)N_USERS * KDIM];  // 32 MB   y_user = x_user @ W (all ratings)
__device__ __half g_y_item[(size_t)N_ITEMS * KDIM];  // 12.8 MB
__device__ int g_cnt[NB];
__device__ int g_scan[NB];
__device__ int g_off[NB + 1];
__device__ int g_cursor[NB];
__device__ int g_bsum[SCAN_NBLK];
__device__ int g_srcids[2 * N_EDGES_C];              // 8 MB

// ============ phase 0: zero bucket counts ============
__global__ void zero_cnt() {
    int i = blockIdx.x * blockDim.x + threadIdx.x;
    int st = gridDim.x * blockDim.x;
    for (int j = i; j < NB; j += st) g_cnt[j] = 0;
}

// ============ phase 1: histogram ============
__global__ void hist_kernel(const int* __restrict__ u_s,
                            const int* __restrict__ v_s,
                            const int* __restrict__ rate) {
    int e = blockIdx.x * blockDim.x + threadIdx.x;
    if (e >= N_EDGES_C) return;
    int u = u_s[e], v = v_s[e], r = rate[e];
    atomicAdd(&g_cnt[u * NR + r], 1);
    atomicAdd(&g_cnt[NBU + v * NR + r], 1);
}

// ============ phase 2a: per-chunk scan ============
__global__ void scan_a() {
    __shared__ int s[SCAN_TPB];
    int t = threadIdx.x;
    int base = blockIdx.x * SCAN_BE + t * SCAN_EPT;
    int v[SCAN_EPT];
    int sum = 0;
    #pragma unroll
    for (int i = 0; i < SCAN_EPT; i++) {
        int idx = base + i;
        int c = (idx < NB) ? g_cnt[idx] : 0;
        v[i] = sum;
        sum += c;
    }
    s[t] = sum;
    __syncthreads();
    for (int d = 1; d < SCAN_TPB; d <<= 1) {
        int x = (t >= d) ? s[t - d] : 0;
        __syncthreads();
        s[t] += x;
        __syncthreads();
    }
    int toff = (t > 0) ? s[t - 1] : 0;
    #pragma unroll
    for (int i = 0; i < SCAN_EPT; i++) {
        int idx = base + i;
        if (idx < NB) g_scan[idx] = toff + v[i];
    }
    if (t == SCAN_TPB - 1) g_bsum[blockIdx.x] = s[t];
}

// ============ phase 2b: apply chunk prefixes (merged) ============
__global__ void scan_bc() {
    __shared__ int s[256];
    int t = threadIdx.x;
    int chunk = blockIdx.x >> 3;
    int x = (t < chunk && t < SCAN_NBLK) ? g_bsum[t] : 0;
    s[t] = x;
    __syncthreads();
    for (int d = 128; d > 0; d >>= 1) {
        if (t < d) s[t] += s[t + d];
        __syncthreads();
    }
    int prefix = s[0];
    int idx = blockIdx.x * 256 + t;
    if (idx < NB) {
        int off = g_scan[idx] + prefix;
        g_off[idx] = off;
        g_cursor[idx] = off;
    }
    if (idx == 0) g_off[NB] = 2 * N_EDGES_C;
}

// ============ phase 3: scatter edge src ids ============
__global__ void scatter_kernel(const int* __restrict__ u_s,
                               const int* __restrict__ v_s,
                               const int* __restrict__ rate) {
    int e = blockIdx.x * blockDim.x + threadIdx.x;
    if (e >= N_EDGES_C) return;
    int u = u_s[e], v = v_s[e], r = rate[e];
    int pu = atomicAdd(&g_cursor[u * NR + r], 1);
    g_srcids[pu] = v;
    int pv = atomicAdd(&g_cursor[NBU + v * NR + r], 1);
    g_srcids[pv] = u;
}

// ============ phase T: y[node] = x[node] @ W[r] for all r, fp16 output ============
#define TM 64
#define T_UBLK ((N_USERS + TM - 1) / TM)   // 782
#define T_IBLK ((N_ITEMS + TM - 1) / TM)   // 313

__device__ __forceinline__ unsigned long long pack2(float a) {
    unsigned long long r;
    asm("mov.b64 %0, {%1, %1};" : "=l"(r) : "r"(__float_as_uint(a)));
    return r;
}
__device__ __forceinline__ void fma2(unsigned long long& d,
                                     unsigned long long a, unsigned long long b) {
    asm("fma.rn.f32x2 %0, %1, %2, %0;" : "+l"(d) : "l"(a), "l"(b));
}

__global__ __launch_bounds__(256) void transform_kernel(const float* __restrict__ x_user,
                                                        const float* __restrict__ x_item,
                                                        const float* __restrict__ W) {
    int b = blockIdx.x;
    const float* x;
    __half* y;
    int M, rowBase;
    if (b < T_UBLK) {
        x = x_user; y = g_y_user; M = N_USERS; rowBase = b * TM;
    } else {
        x = x_item; y = g_y_item; M = N_ITEMS; rowBase = (b - T_UBLK) * TM;
    }

    __shared__ __align__(16) float Xst[F][TM + 2];   // transposed x tile: [k][row]
    __shared__ __align__(16) float Ws[F][HID];       // 64 x 64 W chunk

    int tid = threadIdx.x;
    // load X tile transposed: thread -> (row = tid>>2, quad = tid&3)
    {
        int row = tid >> 2;
        int quad = tid & 3;
        int grow = rowBase + row;
        const float4* xp = (const float4*)(x + (size_t)grow * F + quad * 16);
        #pragma unroll
        for (int h = 0; h < 4; h++) {
            float4 v = (grow < M) ? xp[h] : make_float4(0.f, 0.f, 0.f, 0.f);
            int k = quad * 16 + h * 4;
            Xst[k + 0][row] = v.x;
            Xst[k + 1][row] = v.y;
            Xst[k + 2][row] = v.z;
            Xst[k + 3][row] = v.w;
        }
    }

    int tx = tid & 15;   // output cols tx*4 .. +3 (within 64-chunk)
    int ty = tid >> 4;   // rows ty*4 .. +3

    for (int r = 0; r < NR; r++) {
        __syncthreads();   // protect Ws reuse across iterations (and Xst on first)
        {
            const float4* wp = (const float4*)(W + (size_t)r * F * HID);
            float4* wsp = (float4*)&Ws[0][0];
            wsp[tid]       = wp[tid];
            wsp[tid + 256] = wp[tid + 256];
            wsp[tid + 512] = wp[tid + 512];
            wsp[tid + 768] = wp[tid + 768];
        }
        __syncthreads();

        unsigned long long acc[2][4];   // [rowpair][col]; pair = rows {2p, 2p+1} of ty*4..
        #pragma unroll
        for (int p = 0; p < 2; p++)
            #pragma unroll
            for (int c = 0; c < 4; c++) acc[p][c] = 0ull;

        #pragma unroll
        for (int k = 0; k < F; k++) {
            unsigned long long a0 = *(const unsigned long long*)&Xst[k][ty * 4];
            unsigned long long a1 = *(const unsigned long long*)&Xst[k][ty * 4 + 2];
            float4 bv = *(const float4*)&Ws[k][tx * 4];
            unsigned long long b0 = pack2(bv.x);
            unsigned long long b1 = pack2(bv.y);
            unsigned long long b2 = pack2(bv.z);
            unsigned long long b3 = pack2(bv.w);
            fma2(acc[0][0], a0, b0); fma2(acc[0][1], a0, b1);
            fma2(acc[0][2], a0, b2); fma2(acc[0][3], a0, b3);
            fma2(acc[1][0], a1, b0); fma2(acc[1][1], a1, b1);
            fma2(acc[1][2], a1, b2); fma2(acc[1][3], a1, b3);
        }

        // store fp16: rowpair p holds rows ty*4+2p (lo) and ty*4+2p+1 (hi)
        #pragma unroll
        for (int p = 0; p < 2; p++) {
            float2 c0 = *(float2*)&acc[p][0];
            float2 c1 = *(float2*)&acc[p][1];
            float2 c2 = *(float2*)&acc[p][2];
            float2 c3 = *(float2*)&acc[p][3];
            int re = rowBase + ty * 4 + 2 * p;
            if (re < M) {
                union { __half2 h[2]; uint2 u; } pk;
                pk.h[0] = __floats2half2_rn(c0.x, c1.x);
                pk.h[1] = __floats2half2_rn(c2.x, c3.x);
                *(uint2*)(y + (size_t)re * KDIM + r * F + tx * 4) = pk.u;
            }
            if (re + 1 < M) {
                union { __half2 h[2]; uint2 u; } pk;
                pk.h[0] = __floats2half2_rn(c0.y, c1.y);
                pk.h[1] = __floats2half2_rn(c2.y, c3.y);
                *(uint2*)(y + (size_t)(re + 1) * KDIM + r * F + tx * 4) = pk.u;
            }
        }
    }
}

// ============ phase 4: gather y-slices + mean, one warp per NODE; writes out ============
__global__ __launch_bounds__(256) void aggregate_kernel(float* __restrict__ out) {
    int wid = (blockIdx.x * blockDim.x + threadIdx.x) >> 5;
    int lane = threadIdx.x & 31;
    if (wid >= N_USERS + N_ITEMS) return;

    int bb;
    const __half* __restrict__ ytab;
    float* orow;
    if (wid < N_USERS) {
        bb = wid * NR;
        ytab = g_y_item;                     // user aggregates item features
        orow = out + (size_t)wid * HID;
    } else {
        int v = wid - N_USERS;
        bb = NBU + v * NR;
        ytab = g_y_user;                     // item aggregates user features
        orow = out + (size_t)(N_USERS + v) * HID;
    }

    // lanes 0..5 fetch the 6 offsets bounding this node's 5 buckets
    int o = (lane <= NR) ? g_off[bb + lane] : 0;

    float tx = 0.f, ty = 0.f;   // this lane's 2 output features (lane*2, lane*2+1)

    #pragma unroll
    for (int r = 0; r < NR; r++) {
        int begin = __shfl_sync(0xffffffffu, o, r);
        int end   = __shfl_sync(0xffffffffu, o, r + 1);
        float ax = 0.f, ay = 0.f;
        int j = begin;
        while (j < end) {
            int mm = min(32, end - j);
            int id = (lane < mm) ? g_srcids[j + lane] : 0;
            int q = 0;
            for (; q + 4 <= mm; q += 4) {
                int s0 = __shfl_sync(0xffffffffu, id, q + 0);
                int s1 = __shfl_sync(0xffffffffu, id, q + 1);
                int s2 = __shfl_sync(0xffffffffu, id, q + 2);
                int s3 = __shfl_sync(0xffffffffu, id, q + 3);
                __half2 h0 = ((const __half2*)(ytab + (size_t)s0 * KDIM + r * F))[lane];
                __half2 h1 = ((const __half2*)(ytab + (size_t)s1 * KDIM + r * F))[lane];
                __half2 h2 = ((const __half2*)(ytab + (size_t)s2 * KDIM + r * F))[lane];
                __half2 h3 = ((const __half2*)(ytab + (size_t)s3 * KDIM + r * F))[lane];
                float2 f0 = __half22float2(h0);
                float2 f1 = __half22float2(h1);
                float2 f2 = __half22float2(h2);
                float2 f3 = __half22float2(h3);
                ax += f0.x + f1.x + f2.x + f3.x;
                ay += f0.y + f1.y + f2.y + f3.y;
            }
            for (; q < mm; q++) {
                int s0 = __shfl_sync(0xffffffffu, id, q);
                float2 f0 = __half22float2(
                    ((const __half2*)(ytab + (size_t)s0 * KDIM + r * F))[lane]);
                ax += f0.x;
                ay += f0.y;
            }
            j += mm;
        }
        int n = end - begin;
        float invc = (n > 0) ? 1.0f / (float)n : 0.0f;
        tx += ax * invc;
        ty += ay * invc;
    }

    ((float2*)orow)[lane] = make_float2(tx, ty);
}

// ============ launch ============
extern "C" void kernel_launch(void* const* d_in, const int* in_sizes, int n_in,
                              void* d_out, int out_size) {
    const int*   u_s    = (const int*)d_in[0];
    const int*   v_s    = (const int*)d_in[1];
    const int*   rate   = (const int*)d_in[2];
    const float* x_user = (const float*)d_in[3];
    const float* x_item = (const float*)d_in[4];
    const float* weight = (const float*)d_in[5];
    float* out = (float*)d_out;
    (void)in_sizes; (void)n_in; (void)out_size;

    int ethreads = 256;
    int eblocks = (N_EDGES_C + ethreads - 1) / ethreads;

    zero_cnt<<<512, 256>>>();
    hist_kernel<<<eblocks, ethreads>>>(u_s, v_s, rate);
    scan_a<<<SCAN_NBLK, SCAN_TPB>>>();
    scan_bc<<<(NB + 255) / 256, 256>>>();
    scatter_kernel<<<eblocks, ethreads>>>(u_s, v_s, rate);

    transform_kernel<<<T_UBLK + T_IBLK, 256>>>(x_user, x_item, weight);

    int nwarps = N_USERS + N_ITEMS;        // one warp per node
    int ablocks = (nwarps + 7) / 8;
    aggregate_kernel<<<ablocks, 256>>>(out);
}